// round 15
// baseline (speedup 1.0000x reference)
#include <cuda_runtime.h>
#include <math.h>

#define BB 16
#define TT 50
#define NGT 800
#define AA 3
#define HH 76
#define WW 76
#define HWX 5776
#define NCELL 277248
#define NCLS 80
#define ATTR 85
#define PRED_B (255*HWX)
#define IGNORE_THR 0.5f

#define NV (NCELL/4)                 // 69312 float4s of conf channel
#define DENSEB ((NV+255)/256)        // 271
#define MASKB 100                    // x8 warps = 800 = NGT
#define NBLK (DENSEB + MASKB)        // 371

__device__ __constant__ float c_aw[3] = {14.5f, 19.5f, 46.625f};
__device__ __constant__ float c_ah[3] = {11.25f, 24.75f, 40.75f};

// ---------------- global scratch (finalizer self-resets everything) ---------
__device__ double        g_acc[3];   // 0: dense conf, 1: obj + 0.5*ignore-sub, 2: cls
__device__ int           g_npos;
__device__ unsigned int  g_done;

// fast softplus: log(1+e^z); |z| <= ~6 here so approx intrinsics are safe
__device__ __forceinline__ float spf(float z) {
    return __logf(1.0f + __expf(z));
}

// Decode core (no target logs). JAX negative-index WRAP semantics:
//  * padded rows -> mask cell (b, anchor0, gj=0, WW-1)
//  * noobj scatter: anchors failing iou>thr (or invalid row) WRAP to anchor 2
struct GTLite {
    int cell, ci, ic0, ic1, ic2;
};

__device__ __forceinline__ GTLite decode_lite(const float* __restrict__ annot,
                                              int b, int t) {
    GTLite o; o.cell = -1; o.ci = -1; o.ic0 = -1; o.ic1 = -1; o.ic2 = -1;
    if (t >= TT) return o;
    const float* an = annot + (b * TT + t) * 5;
    float a0 = an[0], a1 = an[1], a2 = an[2], a3 = an[3], a4 = an[4];
    bool valid = (a0 + a1 + a2 + a3 + a4) != 0.0f;
    float gx = a1 * (float)WW, gy = a2 * (float)HH;
    float gw = a3 * (float)WW, gh = a4 * (float)HH;
    int gi = (int)floorf(gx), gj = (int)floorf(gy);
    const float eps = 1e-9f;
    float best = -1.0f; int bn = 0; float ious[3];
    #pragma unroll
    for (int a = 0; a < 3; ++a) {
        float inter = fminf(gw, c_aw[a]) * fminf(gh, c_ah[a]);
        float un = gw * (gh + eps) + c_aw[a] * (c_ah[a] + eps) - inter + eps;
        ious[a] = inter / un;
        if (ious[a] > best) { best = ious[a]; bn = a; }    // first max
    }
    if (gi >= 0 && gi < WW && gj >= 0 && gj < HH) {
        int base = b * AA * HWX + gj * WW + gi;
        o.ic0 = base + (((ious[0] > IGNORE_THR) && valid) ? 0 : 2) * HWX;
        o.ic1 = base + (((ious[1] > IGNORE_THR) && valid) ? 1 : 2) * HWX;
        o.ic2 = base + 2 * HWX;                            // a=2 wraps to itself
    }
    int ii = valid ? gi : (WW - 1);                        // wrap to WW-1
    if (ii >= 0 && ii < WW && gj >= 0 && gj < HH)
        o.cell = (b * AA + bn) * HWX + gj * WW + ii;
    o.ci = (int)a0;                                        // 0 for padded rows
    return o;
}

// Own-GT targets (only the winner's lane 0 consumes these)
__device__ __forceinline__ void decode_targets(const float* __restrict__ annot,
                                               int b, int t,
                                               float& tx, float& ty,
                                               float& tw, float& th) {
    const float* an = annot + (b * TT + t) * 5;
    float a1 = an[1], a2 = an[2], a3 = an[3], a4 = an[4];
    float gx = a1 * (float)WW, gy = a2 * (float)HH;
    float gw = a3 * (float)WW, gh = a4 * (float)HH;
    int gi = (int)floorf(gx), gj = (int)floorf(gy);
    const float eps = 1e-9f;
    float best = -1.0f; int bn = 0;
    #pragma unroll
    for (int a = 0; a < 3; ++a) {
        float inter = fminf(gw, c_aw[a]) * fminf(gh, c_ah[a]);
        float un = gw * (gh + eps) + c_aw[a] * (c_ah[a] + eps) - inter + eps;
        float iou = inter / un;
        if (iou > best) { best = iou; bn = a; }
    }
    tx = gx - (float)gi;
    ty = gy - (float)gj;
    tw = __logf(gw / c_aw[bn] + 1e-16f);
    th = __logf(gh / c_ah[bn] + 1e-16f);
}

__global__ void __launch_bounds__(256)
k_all(const float* __restrict__ pred, const float* __restrict__ annot,
      float* __restrict__ out, int out_n) {
    __shared__ double s_obj, s_cls, s_dense;
    __shared__ int    s_np;
    __shared__ double sh[8];

    const int tid = threadIdx.x;
    const int bid = blockIdx.x;
    const unsigned F = 0xffffffffu;

    if (bid < DENSEB) {
        // ========== DENSE: unconditional sum spf(conf) over ALL cells =======
        int t4 = bid * 256 + tid;
        double s = 0.0;
        if (t4 < NV) {
            const int V_ROW = HWX / 4;                     // 1444
            int r = t4 / V_ROW;
            int v = t4 - r * V_ROW;
            int b = r / AA, a = r - b * AA;
            const float4 f = *reinterpret_cast<const float4*>(
                pred + (size_t)b * PRED_B + (size_t)(a * ATTR + 4) * HWX + 4 * v);
            // max factor ~ 1+e^5.6 ~ 271; product of 4 < 5.4e9, safe in float
            float prod = (1.0f + __expf(f.x)) * (1.0f + __expf(f.y))
                       * (1.0f + __expf(f.z)) * (1.0f + __expf(f.w));
            s = (double)__logf(prod);
        }
        #pragma unroll
        for (int o = 16; o; o >>= 1) s += __shfl_down_sync(F, s, o);
        int lane = tid & 31, wid = tid >> 5;
        if (lane == 0) sh[wid] = s;
        __syncthreads();
        if (tid == 0) {
            double t = 0.0;
            #pragma unroll
            for (int w = 0; w < 8; ++w) t += sh[w];
            atomicAdd(&g_acc[0], t);
        }
    } else {
        // ========== MASK: one warp per GT ====================================
        if (tid == 0) { s_obj = 0.0; s_cls = 0.0; s_np = 0; }
        __syncthreads();

        int g = (bid - DENSEB) * 8 + (tid >> 5);           // 0..799
        int lane = tid & 31;
        int b = g / TT, myt = g - b * TT;

        // --- own decode first (no cross-lane dependency) ---
        GTLite me = decode_lite(annot, b, myt);

        // --- issue ALL scattered loads immediately; they fly during ballots --
        float z0 = 0.f, z1 = 0.f, z2 = 0.f, zhead = 0.f, zsub = 0.f;
        if (me.cell >= 0) {
            int pix = me.cell % HWX;
            int ra = me.cell / HWX;
            int bb = ra / AA, aa = ra - bb * AA;
            const float* base = pred + (size_t)bb * PRED_B + (size_t)(aa * ATTR) * HWX;
            z0 = base[(size_t)(5  + lane) * HWX + pix];
            z1 = base[(size_t)(37 + lane) * HWX + pix];
            if (lane < 16) z2 = base[(size_t)(69 + lane) * HWX + pix];
            if (lane < 5)  zhead = base[(size_t)lane * HWX + pix];
        }
        int micL = (lane == 0) ? me.ic0 : (lane == 1) ? me.ic1 : me.ic2;
        if (lane < 3 && micL >= 0) {
            int pixs = micL % HWX;
            int ras = micL / HWX;
            int bs = ras / AA, as_ = ras - bs * AA;
            zsub = pred[(size_t)bs * PRED_B + (size_t)(as_ * ATTR + 4) * HWX + pixs];
        }

        // --- collective light decodes (overlap the loads) -----
        GTLite A = decode_lite(annot, b, lane);
        GTLite Bx = decode_lite(annot, b, lane + 32);

        // --- last-wins winner ---
        unsigned mA = __ballot_sync(F, A.cell >= 0 && A.cell == me.cell);
        unsigned mB = __ballot_sync(F, Bx.cell >= 0 && Bx.cell == me.cell);
        int last = mB ? 32 + (31 - __clz(mB)) : (mA ? (31 - __clz(mA)) : -1);
        bool winner = (me.cell >= 0) && (last == myt);

        // --- merged class bits of my cell ---
        bool hitA = (A.cell >= 0 && A.cell == me.cell && A.ci >= 0 && A.ci < NCLS);
        bool hitB = (Bx.cell >= 0 && Bx.cell == me.cell && Bx.ci >= 0 && Bx.ci < NCLS);
        unsigned w0 = __reduce_or_sync(F, (hitA && (A.ci >> 5) == 0) ? (1u << (A.ci & 31)) : 0u)
                    | __reduce_or_sync(F, (hitB && (Bx.ci >> 5) == 0) ? (1u << (Bx.ci & 31)) : 0u);
        unsigned w1 = __reduce_or_sync(F, (hitA && (A.ci >> 5) == 1) ? (1u << (A.ci & 31)) : 0u)
                    | __reduce_or_sync(F, (hitB && (Bx.ci >> 5) == 1) ? (1u << (Bx.ci & 31)) : 0u);
        unsigned w2 = __reduce_or_sync(F, (hitA && (A.ci >> 5) == 2) ? (1u << (A.ci & 31)) : 0u)
                    | __reduce_or_sync(F, (hitB && (Bx.ci >> 5) == 2) ? (1u << (Bx.ci & 31)) : 0u);

        // --- ignore-cell responsibility (first producer subtracts) ---
        unsigned earlyA = (myt >= 32) ? F : ((myt == 0) ? 0u : ((1u << myt) - 1u));
        unsigned earlyB = (myt <= 32) ? 0u : ((1u << (myt - 32)) - 1u);
        unsigned dA0 = __ballot_sync(F, A.ic0 == me.ic0 || A.ic1 == me.ic0 || A.ic2 == me.ic0) & earlyA;
        unsigned dB0 = __ballot_sync(F, Bx.ic0 == me.ic0 || Bx.ic1 == me.ic0 || Bx.ic2 == me.ic0) & earlyB;
        unsigned dA1 = __ballot_sync(F, A.ic0 == me.ic1 || A.ic1 == me.ic1 || A.ic2 == me.ic1) & earlyA;
        unsigned dB1 = __ballot_sync(F, Bx.ic0 == me.ic1 || Bx.ic1 == me.ic1 || Bx.ic2 == me.ic1) & earlyB;
        unsigned dA2 = __ballot_sync(F, A.ic0 == me.ic2 || A.ic1 == me.ic2 || A.ic2 == me.ic2) & earlyA;
        unsigned dB2 = __ballot_sync(F, Bx.ic0 == me.ic2 || Bx.ic1 == me.ic2 || Bx.ic2 == me.ic2) & earlyB;
        bool r0 = (me.ic0 >= 0) && !(dA0 | dB0);
        bool r1 = (me.ic1 >= 0) && (me.ic1 != me.ic0) && !(dA1 | dB1);
        bool r2 = (me.ic2 >= 0) && (me.ic2 != me.ic0) && (me.ic2 != me.ic1) && !(dA2 | dB2);

        double lobj = 0.0, lcls = 0.0;
        bool rr = (lane == 0) ? r0 : (lane == 1) ? r1 : r2;
        if (lane < 3 && rr)
            lobj -= 0.5 * (double)spf(zsub);               // 0.5 factor folded here

        // head values to all lanes (shfl needs full participation)
        float zx = __shfl_sync(F, zhead, 0);
        float zy = __shfl_sync(F, zhead, 1);
        float zw_ = __shfl_sync(F, zhead, 2);
        float zh = __shfl_sync(F, zhead, 3);
        float zc = __shfl_sync(F, zhead, 4);

        int npadd = 0;
        if (winner) {
            lcls += (double)(((w0 >> lane) & 1u) ? spf(-z0) : spf(z0));
            lcls += (double)(((w1 >> lane) & 1u) ? spf(-z1) : spf(z1));
            if (lane < 16)
                lcls += (double)(((w2 >> lane) & 1u) ? spf(-z2) : spf(z2));
            if (lane == 0) {
                npadd = 1;
                float tx, ty, tw, th;
                decode_targets(annot, b, myt, tx, ty, tw, th);
                double lxy = (double)(tx * spf(-zx) + (1.0f - tx) * spf(zx))
                           + (double)(ty * spf(-zy) + (1.0f - ty) * spf(zy));
                double lwh = (double)((zw_ - tw) * (zw_ - tw)
                                    + (zh - th) * (zh - th));
                lobj += 0.5 * lxy + 2.5 * lwh + (double)spf(-zc);
            }
        }

        // warp reduce, then SHARED accumulation (one global atomic pair/block)
        #pragma unroll
        for (int o = 16; o; o >>= 1) {
            lobj += __shfl_down_sync(F, lobj, o);
            lcls += __shfl_down_sync(F, lcls, o);
        }
        if (lane == 0) {
            if (lobj != 0.0) atomicAdd(&s_obj, lobj);
            if (lcls != 0.0) atomicAdd(&s_cls, lcls);
            if (npadd) atomicAdd(&s_np, 1);
        }
        __syncthreads();
        if (tid == 0) {
            if (s_obj != 0.0) atomicAdd(&g_acc[1], s_obj);
            if (s_cls != 0.0) atomicAdd(&g_acc[2], s_cls);
            if (s_np) atomicAdd(&g_npos, s_np);
        }
    }

    // ========== last-block finalize + replay-safe reset ======================
    if (tid == 0) {
        __threadfence();
        unsigned int prev = atomicAdd(&g_done, 1u);
        if (prev == (unsigned int)(NBLK - 1)) {
            const double Nd = (double)NCELL;
            double loss = (0.5 * g_acc[0] + g_acc[1]) / Nd
                        + g_acc[2] / ((double)g_npos * (double)NCLS);
            float v = (float)loss;
            for (int i = 0; i < out_n; ++i) out[i] = v;
            g_acc[0] = 0.0; g_acc[1] = 0.0; g_acc[2] = 0.0;
            g_npos = 0;
            g_done = 0u;
        }
    }
}

extern "C" void kernel_launch(void* const* d_in, const int* in_sizes, int n_in,
                              void* d_out, int out_size) {
    const float* pred;
    const float* annot;
    if (n_in >= 2 && in_sizes[1] > in_sizes[0]) {
        pred  = (const float*)d_in[1];
        annot = (const float*)d_in[0];
    } else {
        pred  = (const float*)d_in[0];
        annot = (const float*)d_in[1];
    }
    k_all<<<NBLK, 256>>>(pred, annot, (float*)d_out, out_size);
}

// round 16
// speedup vs baseline: 1.1600x; 1.1600x over previous
#include <cuda_runtime.h>
#include <math.h>

#define BB 16
#define TT 50
#define NGT 800
#define AA 3
#define HH 76
#define WW 76
#define HWX 5776
#define NCELL 277248
#define NCLS 80
#define ATTR 85
#define PRED_B (255*HWX)
#define IGNORE_THR 0.5f

#define NV (NCELL/4)                 // 69312 float4s of conf channel
#define DENSEB ((NV+255)/256)        // 271
#define MASKB 100                    // x8 warps = 800 = NGT
#define NBLK (DENSEB + MASKB)        // 371

__device__ __constant__ float c_aw[3] = {14.5f, 19.5f, 46.625f};
__device__ __constant__ float c_ah[3] = {11.25f, 24.75f, 40.75f};

// ---------------- global scratch (finalizer self-resets everything) ---------
__device__ double        g_acc[3];   // 0: dense conf, 1: obj + 0.5*ignore-sub, 2: cls
__device__ int           g_npos;
__device__ unsigned int  g_done;

// fast softplus: log(1+e^z); |z| <= ~6 here so approx intrinsics are safe
__device__ __forceinline__ float spf(float z) {
    return __logf(1.0f + __expf(z));
}

// Decode core (no target logs). JAX negative-index WRAP semantics:
//  * padded rows -> mask cell (b, anchor0, gj=0, WW-1)
//  * noobj scatter: anchors failing iou>thr (or invalid row) WRAP to anchor 2
struct GTLite {
    int cell, ci, ic0, ic1, ic2;
};

__device__ __forceinline__ GTLite decode_lite(const float* __restrict__ annot,
                                              int b, int t) {
    GTLite o; o.cell = -1; o.ci = -1; o.ic0 = -1; o.ic1 = -1; o.ic2 = -1;
    if (t >= TT) return o;
    const float* an = annot + (b * TT + t) * 5;
    float a0 = an[0], a1 = an[1], a2 = an[2], a3 = an[3], a4 = an[4];
    bool valid = (a0 + a1 + a2 + a3 + a4) != 0.0f;
    float gx = a1 * (float)WW, gy = a2 * (float)HH;
    float gw = a3 * (float)WW, gh = a4 * (float)HH;
    int gi = (int)floorf(gx), gj = (int)floorf(gy);
    const float eps = 1e-9f;
    float best = -1.0f; int bn = 0; float ious[3];
    #pragma unroll
    for (int a = 0; a < 3; ++a) {
        float inter = fminf(gw, c_aw[a]) * fminf(gh, c_ah[a]);
        float un = gw * (gh + eps) + c_aw[a] * (c_ah[a] + eps) - inter + eps;
        ious[a] = inter / un;
        if (ious[a] > best) { best = ious[a]; bn = a; }    // first max
    }
    if (gi >= 0 && gi < WW && gj >= 0 && gj < HH) {
        int base = b * AA * HWX + gj * WW + gi;
        o.ic0 = base + (((ious[0] > IGNORE_THR) && valid) ? 0 : 2) * HWX;
        o.ic1 = base + (((ious[1] > IGNORE_THR) && valid) ? 1 : 2) * HWX;
        o.ic2 = base + 2 * HWX;                            // a=2 wraps to itself
    }
    int ii = valid ? gi : (WW - 1);                        // wrap to WW-1
    if (ii >= 0 && ii < WW && gj >= 0 && gj < HH)
        o.cell = (b * AA + bn) * HWX + gj * WW + ii;
    o.ci = (int)a0;                                        // 0 for padded rows
    return o;
}

// Own-GT targets (only the winner's lane 0 consumes these)
__device__ __forceinline__ void decode_targets(const float* __restrict__ annot,
                                               int b, int t,
                                               float& tx, float& ty,
                                               float& tw, float& th) {
    const float* an = annot + (b * TT + t) * 5;
    float a1 = an[1], a2 = an[2], a3 = an[3], a4 = an[4];
    float gx = a1 * (float)WW, gy = a2 * (float)HH;
    float gw = a3 * (float)WW, gh = a4 * (float)HH;
    int gi = (int)floorf(gx), gj = (int)floorf(gy);
    const float eps = 1e-9f;
    float best = -1.0f; int bn = 0;
    #pragma unroll
    for (int a = 0; a < 3; ++a) {
        float inter = fminf(gw, c_aw[a]) * fminf(gh, c_ah[a]);
        float un = gw * (gh + eps) + c_aw[a] * (c_ah[a] + eps) - inter + eps;
        float iou = inter / un;
        if (iou > best) { best = iou; bn = a; }
    }
    tx = gx - (float)gi;
    ty = gy - (float)gj;
    tw = __logf(gw / c_aw[bn] + 1e-16f);
    th = __logf(gh / c_ah[bn] + 1e-16f);
}

__global__ void __launch_bounds__(256)
k_all(const float* __restrict__ pred, const float* __restrict__ annot,
      float* __restrict__ out, int out_n) {
    __shared__ double sh[8];

    const int tid = threadIdx.x;
    const int bid = blockIdx.x;
    const unsigned F = 0xffffffffu;

    if (bid < MASKB) {
        // ========== MASK: one warp per GT (scheduled FIRST: longest chain) ===
        int g = bid * 8 + (tid >> 5);                      // 0..799
        int lane = tid & 31;
        int b = g / TT, myt = g - b * TT;

        // --- own decode first (no cross-lane dependency) ---
        GTLite me = decode_lite(annot, b, myt);

        // --- issue ALL scattered loads immediately; they fly during ballots --
        float z0 = 0.f, z1 = 0.f, z2 = 0.f, zhead = 0.f, zsub = 0.f;
        if (me.cell >= 0) {
            int pix = me.cell % HWX;
            int ra = me.cell / HWX;
            int bb = ra / AA, aa = ra - bb * AA;
            const float* base = pred + (size_t)bb * PRED_B + (size_t)(aa * ATTR) * HWX;
            z0 = base[(size_t)(5  + lane) * HWX + pix];
            z1 = base[(size_t)(37 + lane) * HWX + pix];
            if (lane < 16) z2 = base[(size_t)(69 + lane) * HWX + pix];
            if (lane < 5)  zhead = base[(size_t)lane * HWX + pix];
        }
        int micL = (lane == 0) ? me.ic0 : (lane == 1) ? me.ic1 : me.ic2;
        if (lane < 3 && micL >= 0) {
            int pixs = micL % HWX;
            int ras = micL / HWX;
            int bs = ras / AA, as_ = ras - bs * AA;
            zsub = pred[(size_t)bs * PRED_B + (size_t)(as_ * ATTR + 4) * HWX + pixs];
        }

        // --- collective light decodes (overlap the loads) -----
        GTLite A = decode_lite(annot, b, lane);
        GTLite Bx = decode_lite(annot, b, lane + 32);

        // --- last-wins winner ---
        unsigned mA = __ballot_sync(F, A.cell >= 0 && A.cell == me.cell);
        unsigned mB = __ballot_sync(F, Bx.cell >= 0 && Bx.cell == me.cell);
        int last = mB ? 32 + (31 - __clz(mB)) : (mA ? (31 - __clz(mA)) : -1);
        bool winner = (me.cell >= 0) && (last == myt);

        // --- merged class bits of my cell ---
        bool hitA = (A.cell >= 0 && A.cell == me.cell && A.ci >= 0 && A.ci < NCLS);
        bool hitB = (Bx.cell >= 0 && Bx.cell == me.cell && Bx.ci >= 0 && Bx.ci < NCLS);
        unsigned w0 = __reduce_or_sync(F, (hitA && (A.ci >> 5) == 0) ? (1u << (A.ci & 31)) : 0u)
                    | __reduce_or_sync(F, (hitB && (Bx.ci >> 5) == 0) ? (1u << (Bx.ci & 31)) : 0u);
        unsigned w1 = __reduce_or_sync(F, (hitA && (A.ci >> 5) == 1) ? (1u << (A.ci & 31)) : 0u)
                    | __reduce_or_sync(F, (hitB && (Bx.ci >> 5) == 1) ? (1u << (Bx.ci & 31)) : 0u);
        unsigned w2 = __reduce_or_sync(F, (hitA && (A.ci >> 5) == 2) ? (1u << (A.ci & 31)) : 0u)
                    | __reduce_or_sync(F, (hitB && (Bx.ci >> 5) == 2) ? (1u << (Bx.ci & 31)) : 0u);

        // --- ignore-cell responsibility (first producer subtracts) ---
        unsigned earlyA = (myt >= 32) ? F : ((myt == 0) ? 0u : ((1u << myt) - 1u));
        unsigned earlyB = (myt <= 32) ? 0u : ((1u << (myt - 32)) - 1u);
        unsigned dA0 = __ballot_sync(F, A.ic0 == me.ic0 || A.ic1 == me.ic0 || A.ic2 == me.ic0) & earlyA;
        unsigned dB0 = __ballot_sync(F, Bx.ic0 == me.ic0 || Bx.ic1 == me.ic0 || Bx.ic2 == me.ic0) & earlyB;
        unsigned dA1 = __ballot_sync(F, A.ic0 == me.ic1 || A.ic1 == me.ic1 || A.ic2 == me.ic1) & earlyA;
        unsigned dB1 = __ballot_sync(F, Bx.ic0 == me.ic1 || Bx.ic1 == me.ic1 || Bx.ic2 == me.ic1) & earlyB;
        unsigned dA2 = __ballot_sync(F, A.ic0 == me.ic2 || A.ic1 == me.ic2 || A.ic2 == me.ic2) & earlyA;
        unsigned dB2 = __ballot_sync(F, Bx.ic0 == me.ic2 || Bx.ic1 == me.ic2 || Bx.ic2 == me.ic2) & earlyB;
        bool r0 = (me.ic0 >= 0) && !(dA0 | dB0);
        bool r1 = (me.ic1 >= 0) && (me.ic1 != me.ic0) && !(dA1 | dB1);
        bool r2 = (me.ic2 >= 0) && (me.ic2 != me.ic0) && (me.ic2 != me.ic1) && !(dA2 | dB2);

        double lobj = 0.0, lcls = 0.0;
        bool rr = (lane == 0) ? r0 : (lane == 1) ? r1 : r2;
        if (lane < 3 && rr)
            lobj -= 0.5 * (double)spf(zsub);               // 0.5 factor folded here

        // head values to all lanes (shfl needs full participation)
        float zx = __shfl_sync(F, zhead, 0);
        float zy = __shfl_sync(F, zhead, 1);
        float zw_ = __shfl_sync(F, zhead, 2);
        float zh = __shfl_sync(F, zhead, 3);
        float zc = __shfl_sync(F, zhead, 4);

        if (winner) {
            lcls += (double)(((w0 >> lane) & 1u) ? spf(-z0) : spf(z0));
            lcls += (double)(((w1 >> lane) & 1u) ? spf(-z1) : spf(z1));
            if (lane < 16)
                lcls += (double)(((w2 >> lane) & 1u) ? spf(-z2) : spf(z2));
            if (lane == 0) {
                atomicAdd(&g_npos, 1);
                float tx, ty, tw, th;
                decode_targets(annot, b, myt, tx, ty, tw, th);
                double lxy = (double)(tx * spf(-zx) + (1.0f - tx) * spf(zx))
                           + (double)(ty * spf(-zy) + (1.0f - ty) * spf(zy));
                double lwh = (double)((zw_ - tw) * (zw_ - tw)
                                    + (zh - th) * (zh - th));
                lobj += 0.5 * lxy + 2.5 * lwh + (double)spf(-zc);
            }
        }

        // warp reduce + direct global atomics (no block barriers here)
        #pragma unroll
        for (int o = 16; o; o >>= 1) {
            lobj += __shfl_down_sync(F, lobj, o);
            lcls += __shfl_down_sync(F, lcls, o);
        }
        if (lane == 0) {
            if (lobj != 0.0) atomicAdd(&g_acc[1], lobj);
            if (lcls != 0.0) atomicAdd(&g_acc[2], lcls);
        }
        __syncthreads();   // all warps' atomics done before the done-counter
    } else {
        // ========== DENSE: unconditional sum spf(conf) over ALL cells =======
        int t4 = (bid - MASKB) * 256 + tid;
        double s = 0.0;
        if (t4 < NV) {
            const int V_ROW = HWX / 4;                     // 1444
            int r = t4 / V_ROW;
            int v = t4 - r * V_ROW;
            int b = r / AA, a = r - b * AA;
            const float4 f = *reinterpret_cast<const float4*>(
                pred + (size_t)b * PRED_B + (size_t)(a * ATTR + 4) * HWX + 4 * v);
            // max factor ~ 1+e^5.6 ~ 271; product of 4 < 5.4e9, safe in float
            float prod = (1.0f + __expf(f.x)) * (1.0f + __expf(f.y))
                       * (1.0f + __expf(f.z)) * (1.0f + __expf(f.w));
            s = (double)__logf(prod);
        }
        #pragma unroll
        for (int o = 16; o; o >>= 1) s += __shfl_down_sync(F, s, o);
        int lane = tid & 31, wid = tid >> 5;
        if (lane == 0) sh[wid] = s;
        __syncthreads();   // single barrier; also orders before done-counter
        if (tid == 0) {
            double t = 0.0;
            #pragma unroll
            for (int w = 0; w < 8; ++w) t += sh[w];
            atomicAdd(&g_acc[0], t);
        }
    }

    // ========== last-block finalize + replay-safe reset ======================
    if (tid == 0) {
        __threadfence();
        unsigned int prev = atomicAdd(&g_done, 1u);
        if (prev == (unsigned int)(NBLK - 1)) {
            const double Nd = (double)NCELL;
            double loss = (0.5 * g_acc[0] + g_acc[1]) / Nd
                        + g_acc[2] / ((double)g_npos * (double)NCLS);
            float v = (float)loss;
            for (int i = 0; i < out_n; ++i) out[i] = v;
            g_acc[0] = 0.0; g_acc[1] = 0.0; g_acc[2] = 0.0;
            g_npos = 0;
            g_done = 0u;
        }
    }
}

extern "C" void kernel_launch(void* const* d_in, const int* in_sizes, int n_in,
                              void* d_out, int out_size) {
    const float* pred;
    const float* annot;
    if (n_in >= 2 && in_sizes[1] > in_sizes[0]) {
        pred  = (const float*)d_in[1];
        annot = (const float*)d_in[0];
    } else {
        pred  = (const float*)d_in[0];
        annot = (const float*)d_in[1];
    }
    k_all<<<NBLK, 256>>>(pred, annot, (float*)d_out, out_size);
}